// round 8
// baseline (speedup 1.0000x reference)
#include <cuda_runtime.h>
#include <cstdint>
#include <cstddef>

// ============================================================================
// LSTM: x (32,512,1024), h0 (32,1024), Wx (1024,4096), Wh (1024,4096), b (4096)
// Phase 1: g_xproj = x @ Wx + b   (tf32 mma.sync, 128x128x16 pipeline)
// Phase 2: ONE persistent kernel, 128 co-resident CTAs, Wh slice resident in
//          SMEM (tf32). h staged via cp.async.bulk (TMA path) + mbarrier:
//          32 x 512B bulk copies per 128-col chunk — removes the LDGSTS
//          issue bottleneck (was 8192 x 16B cp.async = ~16K cyc/SMSP/step).
//          Dataflow sync via per-CTA monotonic flags (no global barrier).
// ============================================================================

#define DI __device__ __forceinline__

DI uint32_t smem_u32(const void* p) { return (uint32_t)__cvta_generic_to_shared(p); }

DI void cp16(const void* smem_dst, const void* gsrc) {
    asm volatile("cp.async.ca.shared.global [%0], [%1], 16;"
                 :: "r"(smem_u32(smem_dst)), "l"(gsrc));
}
DI void cp_commit() { asm volatile("cp.async.commit_group;"); }
template<int N> DI void cp_wait() { asm volatile("cp.async.wait_group %0;" :: "n"(N)); }

DI uint32_t f2tf32(float f) {
    uint32_t u;
    asm("cvt.rna.tf32.f32 %0, %1;" : "=r"(u) : "f"(f));
    return u;
}

DI unsigned ld_acq_gpu(const unsigned* p) {
    unsigned v;
    asm volatile("ld.acquire.gpu.u32 %0, [%1];" : "=r"(v) : "l"(p));
    return v;
}
DI void st_rel_gpu(unsigned* p, unsigned v) {
    asm volatile("st.release.gpu.u32 [%0], %1;" :: "l"(p), "r"(v) : "memory");
}

DI void mma_tf32(float* c, const uint32_t* a, const uint32_t* b) {
    asm volatile(
        "mma.sync.aligned.m16n8k8.row.col.f32.tf32.tf32.f32 "
        "{%0,%1,%2,%3}, {%4,%5,%6,%7}, {%8,%9}, {%0,%1,%2,%3};"
        : "+f"(c[0]), "+f"(c[1]), "+f"(c[2]), "+f"(c[3])
        : "r"(a[0]), "r"(a[1]), "r"(a[2]), "r"(a[3]), "r"(b[0]), "r"(b[1]));
}

DI float fast_sigmoid(float x) { return 1.f / (1.f + __expf(-x)); }
DI float fast_tanh(float x) {
    float e = __expf(-2.f * x);
    return (1.f - e) / (1.f + e);
}

// ---- bulk-async (TMA path) + mbarrier primitives ----
DI void mbar_init(uint32_t mbar, uint32_t cnt) {
    asm volatile("mbarrier.init.shared.b64 [%0], %1;" :: "r"(mbar), "r"(cnt) : "memory");
}
DI void mbar_expect_tx(uint32_t mbar, uint32_t tx) {
    asm volatile("mbarrier.arrive.expect_tx.shared.b64 _, [%0], %1;"
                 :: "r"(mbar), "r"(tx) : "memory");
}
DI void mbar_wait(uint32_t mbar, uint32_t parity) {
    asm volatile(
        "{\n\t.reg .pred P;\n"
        "W%=:\n\t"
        "mbarrier.try_wait.parity.acquire.cta.shared::cta.b64 P, [%0], %1;\n\t"
        "@P bra D%=;\n\t"
        "bra W%=;\n"
        "D%=:\n\t}"
        :: "r"(mbar), "r"(parity) : "memory");
}
DI void bulk_g2s(uint32_t dst, const void* src, uint32_t bytes, uint32_t mbar) {
    asm volatile(
        "cp.async.bulk.shared::cluster.global.mbarrier::complete_tx::bytes "
        "[%0], [%1], %2, [%3];"
        :: "r"(dst), "l"(src), "r"(bytes), "r"(mbar) : "memory");
}
DI void fence_proxy_async_all() { asm volatile("fence.proxy.async;" ::: "memory"); }

// Scratch (allocation-free rule: __device__ globals)
__device__ float g_xproj[16384 * 4096];   // 256 MB: (N*T, 4H)
__device__ unsigned g_flags[128 * 32];    // per-CTA completed-step counters, 128B apart

// ----------------------------------------------------------------------------
// Phase 1: xproj = X(16384x1024) @ Wx(1024x4096) + b  (unchanged)
// ----------------------------------------------------------------------------
__global__ void __launch_bounds__(256) xproj_kernel(
    const float* __restrict__ X, const float* __restrict__ Wx,
    const float* __restrict__ bias)
{
    __shared__ float sA[2][128][20];
    __shared__ float sB[2][16][136];

    const int tid   = threadIdx.x;
    const int mBase = blockIdx.y * 128;
    const int nBase = blockIdx.x * 128;

    auto load_stage = [&](int s, int k0) {
#pragma unroll
        for (int i = tid; i < 512; i += 256) {
            int r = i >> 2, c = (i & 3) << 2;
            cp16(&sA[s][r][c], X + (size_t)(mBase + r) * 1024 + k0 + c);
        }
#pragma unroll
        for (int i = tid; i < 512; i += 256) {
            int r = i >> 5, c = (i & 31) << 2;
            cp16(&sB[s][r][c], Wx + (size_t)(k0 + r) * 4096 + nBase + c);
        }
        cp_commit();
    };

    load_stage(0, 0);

    const int warp = tid >> 5, lane = tid & 31;
    const int wm = (warp >> 2) * 64, wn = (warp & 3) * 32;
    const int gid = lane >> 2, tig = lane & 3;

    float acc[4][4][4];
#pragma unroll
    for (int mi = 0; mi < 4; ++mi)
#pragma unroll
        for (int ni = 0; ni < 4; ++ni)
#pragma unroll
            for (int r = 0; r < 4; ++r) acc[mi][ni][r] = 0.f;

    for (int kt = 0; kt < 64; ++kt) {
        const int cur = kt & 1;
        cp_wait<0>();
        __syncthreads();
        if (kt < 63) load_stage(cur ^ 1, (kt + 1) * 16);

#pragma unroll
        for (int kk = 0; kk < 16; kk += 8) {
            uint32_t af[4][4], bf[4][2];
#pragma unroll
            for (int mi = 0; mi < 4; ++mi) {
                int r = wm + mi * 16 + gid;
                af[mi][0] = f2tf32(sA[cur][r][kk + tig]);
                af[mi][1] = f2tf32(sA[cur][r + 8][kk + tig]);
                af[mi][2] = f2tf32(sA[cur][r][kk + tig + 4]);
                af[mi][3] = f2tf32(sA[cur][r + 8][kk + tig + 4]);
            }
#pragma unroll
            for (int ni = 0; ni < 4; ++ni) {
                int cc = wn + ni * 8 + gid;
                bf[ni][0] = f2tf32(sB[cur][kk + tig][cc]);
                bf[ni][1] = f2tf32(sB[cur][kk + tig + 4][cc]);
            }
#pragma unroll
            for (int mi = 0; mi < 4; ++mi)
#pragma unroll
                for (int ni = 0; ni < 4; ++ni)
                    mma_tf32(acc[mi][ni], af[mi], bf[ni]);
        }
    }

#pragma unroll
    for (int mi = 0; mi < 4; ++mi) {
#pragma unroll
        for (int ni = 0; ni < 4; ++ni) {
            int row = mBase + wm + mi * 16 + gid;
            int col = nBase + wn + ni * 8 + tig * 2;
            float b0 = bias[col], b1 = bias[col + 1];
            float* p0 = g_xproj + (size_t)row * 4096 + col;
            p0[0] = acc[mi][ni][0] + b0;
            p0[1] = acc[mi][ni][1] + b1;
            float* p1 = g_xproj + (size_t)(row + 8) * 4096 + col;
            p1[0] = acc[mi][ni][2] + b0;
            p1[1] = acc[mi][ni][3] + b1;
        }
    }
}

// ----------------------------------------------------------------------------
__global__ void init_kernel() {
    int i = blockIdx.x * 256 + threadIdx.x;
    if (i < 128 * 32) g_flags[i] = 0u;
}

// ----------------------------------------------------------------------------
// Phase 2: persistent recurrence, bulk-async h staging.
// SMEM layout (dynamic, 231488 B total):
//   [0, 163840)          sWh  (tf32, 1024x32, stride 40) — resident
//   [163840, 163904)     4 mbarriers (8 B each) + pad
//   [163904, 231488)     sH: 4 stages x 32 x 132 fp32 (TMA writes 512 B/row,
//                        rows 528 B apart); partials 8x32x40 alias this region
// Chunk ch (k-cols [128ch,128ch+128)): stage ch&3. Per step, stage s is used
// twice: parity 0 (p=s), parity 1 (p=s+4) — constant across steps.
// Issuing warp for chunk ch is warp ch (preloads 0-2 at step top, 3-7 in-loop).
// ----------------------------------------------------------------------------
static const int SWH_BYTES   = 1024 * 40 * 4;                 // 163840
static const int MBAR_OFF    = SWH_BYTES;                     // 163840
static const int SH_OFF      = SWH_BYTES + 64;                // 163904
static const int STAGE_BYTES = 32 * 132 * 4;                  // 16896
static const int SMEM_BYTES  = SH_OFF + 4 * STAGE_BYTES;      // 231488

__global__ void __launch_bounds__(256, 1) lstm_persist(
    const float* __restrict__ Wh, const float* __restrict__ h0,
    float* __restrict__ out)
{
    extern __shared__ __align__(16) char dyn[];
    uint32_t (*sWh)[40]   = reinterpret_cast<uint32_t (*)[40]>(dyn);
    float (*sH)[32][132]  = reinterpret_cast<float (*)[32][132]>(dyn + SH_OFF);
    float (*part)[32][40] = reinterpret_cast<float (*)[32][40]>(dyn + SH_OFF);
    const uint32_t mbar0  = smem_u32(dyn + MBAR_OFF);
    const uint32_t sh0    = smem_u32(dyn + SH_OFF);

    const int tid = threadIdx.x;
    const int cta = blockIdx.x;
    const int c8  = cta * 8;

    // One-time: resident Wh slice, pre-converted to tf32.
    for (int idx = tid; idx < 1024 * 32; idx += 256) {
        int row = idx >> 5, col = idx & 31;
        int q = col >> 3, jj = col & 7;
        sWh[row][col] = f2tf32(__ldg(Wh + (size_t)row * 4096 + q * 1024 + c8 + jj));
    }
    if (tid == 0) {
#pragma unroll
        for (int s = 0; s < 4; ++s) mbar_init(mbar0 + s * 8, 1);
    }
    __syncthreads();
    fence_proxy_async_all();   // mbarrier init visible to async proxy

    const int warp = tid >> 5, lane = tid & 31;
    const int gid = lane >> 2, tig = lane & 3;
    const int kw = warp * 16;                  // warp's k-cols within a chunk
    const int bb = tid >> 3;                   // batch row 0..31 (epilogue)
    const int jb = tid & 7;                    // gate sub-col 0..7

    float creg = 0.f;

    for (int t = 0; t < 512; ++t) {
        const float* hp;
        size_t hstride;
        if (t == 0) { hp = h0;                           hstride = 1024; }
        else        { hp = out + (size_t)(t - 1) * 1024; hstride = (size_t)512 * 1024; }

        // Prefetch xproj for this thread (consumed at epilogue)
        const float* xpp = g_xproj + ((size_t)bb * 512 + t) * 4096 + c8 + jb;
        float xp0 = __ldg(xpp);
        float xp1 = __ldg(xpp + 1024);
        float xp2 = __ldg(xpp + 2048);
        float xp3 = __ldg(xpp + 3072);

        // Issue chunk ch: poll producers, then 32 bulk copies (one per row).
        // Executed by ONE warp (all 32 lanes participate).
        auto issue_chunk = [&](int ch) {
            if (t > 0) {
                const unsigned* fl = &g_flags[(16 * ch + (lane & 15)) * 32];
                while (ld_acq_gpu(fl) < (unsigned)t) { }
            }
            fence_proxy_async_all();           // order acquired data vs TMA reads
            const uint32_t mb = mbar0 + (ch & 3) * 8;
            if (lane == 0) mbar_expect_tx(mb, 16384);
            __syncwarp();
            const uint32_t dst = sh0 + (uint32_t)(ch & 3) * STAGE_BYTES + lane * 528;
            const char* src = (const char*)hp + (size_t)lane * hstride * 4 + ch * 512;
            bulk_g2s(dst, src, 512, mb);
        };

        if (warp < 3) issue_chunk(warp);       // preload chunks 0,1,2

        float acc[2][4][4];
#pragma unroll
        for (int mi = 0; mi < 2; ++mi)
#pragma unroll
            for (int ni = 0; ni < 4; ++ni)
#pragma unroll
                for (int r = 0; r < 4; ++r) acc[mi][ni][r] = 0.f;

#pragma unroll
        for (int p = 0; p < 8; ++p) {
            __syncthreads();                   // stage (p-1)&3 fully consumed
            if (p < 5 && warp == p + 3) issue_chunk(p + 3);
            mbar_wait(mbar0 + (p & 3) * 8, (p >> 2) & 1);

#pragma unroll
            for (int sub = 0; sub < 2; ++sub) {
                const int kk = kw + sub * 8;       // col within 128-chunk
                const int kg = p * 128 + kk;       // global k (Wh row)
                uint32_t af[2][4], bf[4][2];
#pragma unroll
                for (int mi = 0; mi < 2; ++mi) {
                    int r = mi * 16 + gid;
                    af[mi][0] = f2tf32(sH[p & 3][r][kk + tig]);
                    af[mi][1] = f2tf32(sH[p & 3][r + 8][kk + tig]);
                    af[mi][2] = f2tf32(sH[p & 3][r][kk + tig + 4]);
                    af[mi][3] = f2tf32(sH[p & 3][r + 8][kk + tig + 4]);
                }
#pragma unroll
                for (int ni = 0; ni < 4; ++ni) {
                    bf[ni][0] = sWh[kg + tig][ni * 8 + gid];
                    bf[ni][1] = sWh[kg + tig + 4][ni * 8 + gid];
                }
#pragma unroll
                for (int mi = 0; mi < 2; ++mi)
#pragma unroll
                    for (int ni = 0; ni < 4; ++ni)
                        mma_tf32(acc[mi][ni], af[mi], bf[ni]);
            }
        }

        __syncthreads();   // all stages consumed; safe to alias partials

#pragma unroll
        for (int mi = 0; mi < 2; ++mi)
#pragma unroll
            for (int ni = 0; ni < 4; ++ni) {
                int r = mi * 16 + gid, c = ni * 8 + tig * 2;
                part[warp][r][c]         = acc[mi][ni][0];
                part[warp][r][c + 1]     = acc[mi][ni][1];
                part[warp][r + 8][c]     = acc[mi][ni][2];
                part[warp][r + 8][c + 1] = acc[mi][ni][3];
            }
        __syncthreads();

        // Reduce partials + xproj -> gates -> cell -> h_t (coalesced store)
        float pre[4] = {xp0, xp1, xp2, xp3};
#pragma unroll
        for (int q = 0; q < 4; ++q) {
            int c = q * 8 + jb;
            float s = 0.f;
#pragma unroll
            for (int w = 0; w < 8; ++w) s += part[w][bb][c];
            pre[q] += s;
        }
        float ig = fast_sigmoid(pre[0]);
        float fg = fast_sigmoid(pre[1]);
        float og = fast_sigmoid(pre[2]);
        float gg = fast_tanh(pre[3]);
        creg = fg * creg + ig * gg;
        out[((size_t)bb * 512 + t) * 1024 + c8 + jb] = og * fast_tanh(creg);

        // ---- Publish: partial reads done + h_t stored -> release flag ----
        __syncthreads();
        if (tid == 0) st_rel_gpu(&g_flags[cta * 32], (unsigned)(t + 1));
    }
}

// ----------------------------------------------------------------------------
extern "C" void kernel_launch(void* const* d_in, const int* in_sizes, int n_in,
                              void* d_out, int out_size)
{
    const float* x  = (const float*)d_in[0];   // (32,512,1024)
    const float* h0 = (const float*)d_in[1];   // (32,1024)
    const float* Wx = (const float*)d_in[2];   // (1024,4096)
    const float* Wh = (const float*)d_in[3];   // (1024,4096)
    const float* b  = (const float*)d_in[4];   // (4096,)
    float* out = (float*)d_out;                // (32,512,1024)

    cudaFuncSetAttribute(lstm_persist,
                         cudaFuncAttributeMaxDynamicSharedMemorySize, SMEM_BYTES);

    dim3 gA(32, 128);
    xproj_kernel<<<gA, 256>>>(x, Wx, b);
    init_kernel<<<16, 256>>>();
    lstm_persist<<<128, 256, SMEM_BYTES>>>(Wh, h0, out);
}

// round 9
// speedup vs baseline: 1.6005x; 1.6005x over previous
#include <cuda_runtime.h>
#include <cuda_fp16.h>
#include <cstdint>
#include <cstddef>

// ============================================================================
// LSTM: x (32,512,1024), h0 (32,1024), Wx (1024,4096), Wh (1024,4096), b (4096)
// Phase 1: g_xproj = x @ Wx + b   (tf32 mma.sync, 128x128x16 pipeline)
// Phase 2: ONE persistent kernel, 128 co-resident CTAs.
//          fp16 m16n8k16 mma (same 10-bit mantissa as tf32, 2x MAC/instr).
//          Wh resident in SMEM as fp16 transposed [n][k] (66 KB).
//          h feedback in fp16 via double-buffered g_hh (halves staging traffic,
//          kills all in-loop cvt). Dataflow sync via per-CTA monotonic flags.
// ============================================================================

#define DI __device__ __forceinline__

DI uint32_t smem_u32(const void* p) { return (uint32_t)__cvta_generic_to_shared(p); }

DI void cp16(const void* smem_dst, const void* gsrc) {
    asm volatile("cp.async.ca.shared.global [%0], [%1], 16;"
                 :: "r"(smem_u32(smem_dst)), "l"(gsrc));
}
DI void cp16cg(const void* smem_dst, const void* gsrc) {
    asm volatile("cp.async.cg.shared.global [%0], [%1], 16;"
                 :: "r"(smem_u32(smem_dst)), "l"(gsrc));
}
DI void cp_commit() { asm volatile("cp.async.commit_group;"); }
template<int N> DI void cp_wait() { asm volatile("cp.async.wait_group %0;" :: "n"(N)); }

DI uint32_t f2tf32(float f) {
    uint32_t u;
    asm("cvt.rna.tf32.f32 %0, %1;" : "=r"(u) : "f"(f));
    return u;
}

DI unsigned ld_acq_gpu(const unsigned* p) {
    unsigned v;
    asm volatile("ld.acquire.gpu.u32 %0, [%1];" : "=r"(v) : "l"(p));
    return v;
}
DI void st_rel_gpu(unsigned* p, unsigned v) {
    asm volatile("st.release.gpu.u32 [%0], %1;" :: "l"(p), "r"(v) : "memory");
}
DI void fence_rel_gpu() { asm volatile("fence.acq_rel.gpu;" ::: "memory"); }

DI void mma_tf32(float* c, const uint32_t* a, const uint32_t* b) {
    asm volatile(
        "mma.sync.aligned.m16n8k8.row.col.f32.tf32.tf32.f32 "
        "{%0,%1,%2,%3}, {%4,%5,%6,%7}, {%8,%9}, {%0,%1,%2,%3};"
        : "+f"(c[0]), "+f"(c[1]), "+f"(c[2]), "+f"(c[3])
        : "r"(a[0]), "r"(a[1]), "r"(a[2]), "r"(a[3]), "r"(b[0]), "r"(b[1]));
}

DI void mma_f16(float* c, const uint32_t* a, const uint32_t* b) {
    asm volatile(
        "mma.sync.aligned.m16n8k16.row.col.f32.f16.f16.f32 "
        "{%0,%1,%2,%3}, {%4,%5,%6,%7}, {%8,%9}, {%0,%1,%2,%3};"
        : "+f"(c[0]), "+f"(c[1]), "+f"(c[2]), "+f"(c[3])
        : "r"(a[0]), "r"(a[1]), "r"(a[2]), "r"(a[3]), "r"(b[0]), "r"(b[1]));
}

DI float fast_sigmoid(float x) { return 1.f / (1.f + __expf(-x)); }
DI float fast_tanh(float x) {
    float e = __expf(-2.f * x);
    return (1.f - e) / (1.f + e);
}

// Scratch (allocation-free rule: __device__ globals)
__device__ float g_xproj[16384 * 4096];      // 256 MB: (N*T, 4H)
__device__ __half g_hh[2][32][1024];         // fp16 h, double-buffered by t parity
__device__ unsigned g_flags[128 * 32];       // per-CTA completed-step counters

// ----------------------------------------------------------------------------
// Phase 1: xproj = X(16384x1024) @ Wx(1024x4096) + b  (unchanged, tf32)
// ----------------------------------------------------------------------------
__global__ void __launch_bounds__(256) xproj_kernel(
    const float* __restrict__ X, const float* __restrict__ Wx,
    const float* __restrict__ bias)
{
    __shared__ float sA[2][128][20];
    __shared__ float sB[2][16][136];

    const int tid   = threadIdx.x;
    const int mBase = blockIdx.y * 128;
    const int nBase = blockIdx.x * 128;

    auto load_stage = [&](int s, int k0) {
#pragma unroll
        for (int i = tid; i < 512; i += 256) {
            int r = i >> 2, c = (i & 3) << 2;
            cp16(&sA[s][r][c], X + (size_t)(mBase + r) * 1024 + k0 + c);
        }
#pragma unroll
        for (int i = tid; i < 512; i += 256) {
            int r = i >> 5, c = (i & 31) << 2;
            cp16(&sB[s][r][c], Wx + (size_t)(k0 + r) * 4096 + nBase + c);
        }
        cp_commit();
    };

    load_stage(0, 0);

    const int warp = tid >> 5, lane = tid & 31;
    const int wm = (warp >> 2) * 64, wn = (warp & 3) * 32;
    const int gid = lane >> 2, tig = lane & 3;

    float acc[4][4][4];
#pragma unroll
    for (int mi = 0; mi < 4; ++mi)
#pragma unroll
        for (int ni = 0; ni < 4; ++ni)
#pragma unroll
            for (int r = 0; r < 4; ++r) acc[mi][ni][r] = 0.f;

    for (int kt = 0; kt < 64; ++kt) {
        const int cur = kt & 1;
        cp_wait<0>();
        __syncthreads();
        if (kt < 63) load_stage(cur ^ 1, (kt + 1) * 16);

#pragma unroll
        for (int kk = 0; kk < 16; kk += 8) {
            uint32_t af[4][4], bf[4][2];
#pragma unroll
            for (int mi = 0; mi < 4; ++mi) {
                int r = wm + mi * 16 + gid;
                af[mi][0] = f2tf32(sA[cur][r][kk + tig]);
                af[mi][1] = f2tf32(sA[cur][r + 8][kk + tig]);
                af[mi][2] = f2tf32(sA[cur][r][kk + tig + 4]);
                af[mi][3] = f2tf32(sA[cur][r + 8][kk + tig + 4]);
            }
#pragma unroll
            for (int ni = 0; ni < 4; ++ni) {
                int cc = wn + ni * 8 + gid;
                bf[ni][0] = f2tf32(sB[cur][kk + tig][cc]);
                bf[ni][1] = f2tf32(sB[cur][kk + tig + 4][cc]);
            }
#pragma unroll
            for (int mi = 0; mi < 4; ++mi)
#pragma unroll
                for (int ni = 0; ni < 4; ++ni)
                    mma_tf32(acc[mi][ni], af[mi], bf[ni]);
        }
    }

#pragma unroll
    for (int mi = 0; mi < 4; ++mi) {
#pragma unroll
        for (int ni = 0; ni < 4; ++ni) {
            int row = mBase + wm + mi * 16 + gid;
            int col = nBase + wn + ni * 8 + tig * 2;
            float b0 = bias[col], b1 = bias[col + 1];
            float* p0 = g_xproj + (size_t)row * 4096 + col;
            p0[0] = acc[mi][ni][0] + b0;
            p0[1] = acc[mi][ni][1] + b1;
            float* p1 = g_xproj + (size_t)(row + 8) * 4096 + col;
            p1[0] = acc[mi][ni][2] + b0;
            p1[1] = acc[mi][ni][3] + b1;
        }
    }
}

// ----------------------------------------------------------------------------
// init: clear flags; seed g_hh[0] = fp16(h0)
// ----------------------------------------------------------------------------
__global__ void init_kernel(const float* __restrict__ h0) {
    int i = blockIdx.x * 256 + threadIdx.x;          // 16*256 = 4096 threads
    if (i < 128 * 32) g_flags[i] = 0u;
    for (int idx = i; idx < 32 * 1024; idx += 4096)
        g_hh[0][idx >> 10][idx & 1023] = __float2half(h0[idx]);
}

// ----------------------------------------------------------------------------
// Phase 2: persistent recurrence, fp16 mma, fp16 h staging.
// SMEM layout (dynamic):
//   [0, 66048)            sWhT: fp16 Wh transposed [32 n][1032 k-halves]
//                         (516-word rows: bank = 4*gid+tig, conflict-free)
//   [66048, 66048+40960)  union{ sHh: 4 stages x 32 x 136 halves (8704 B each),
//                                partials 8x32x40 fp32 (40960 B) }
// Per chunk (128 k-cols) per warp: one K16 group (kw = warp*16):
//   af: 8 packed-half2 LDS.32, bf: 8 LDS.32, 8 mma. No cvt.
// ----------------------------------------------------------------------------
static const int SWHT_STRIDE = 1032;                       // halves per n-row
static const int SWHT_BYTES  = 32 * SWHT_STRIDE * 2;       // 66048
static const int STAGE_HALF_STRIDE = 136;                  // halves per h-row
static const int STAGE_BYTES = 32 * STAGE_HALF_STRIDE * 2; // 8704
static const int PART_BYTES  = 8 * 32 * 40 * 4;            // 40960
static const int SMEM_BYTES  = SWHT_BYTES + PART_BYTES;    // 107008

__global__ void __launch_bounds__(256, 1) lstm_persist(
    const float* __restrict__ Wh, float* __restrict__ out)
{
    extern __shared__ __align__(16) char dyn[];
    __half (*sWhT)[SWHT_STRIDE] = reinterpret_cast<__half (*)[SWHT_STRIDE]>(dyn);
    __half (*sHh)[32][STAGE_HALF_STRIDE] =
        reinterpret_cast<__half (*)[32][STAGE_HALF_STRIDE]>(dyn + SWHT_BYTES);
    float (*part)[32][40] = reinterpret_cast<float (*)[32][40]>(dyn + SWHT_BYTES);

    const int tid = threadIdx.x;
    const int cta = blockIdx.x;
    const int c8  = cta * 8;
    const int chOff = cta >> 4;                // stagger: start on own cohort

    // One-time: resident Wh slice as fp16, transposed [n][k].
    // n = q*8 + jj maps to gate column q*1024 + c8 + jj.
    for (int idx = tid; idx < 32 * 1024; idx += 256) {
        int k = idx >> 5, col = idx & 31;      // warp-wide: same k, 32 cols
        int q = col >> 3, jj = col & 7;
        sWhT[col][k] = __float2half(Wh[(size_t)k * 4096 + q * 1024 + c8 + jj]);
    }
    __syncthreads();

    const int warp = tid >> 5, lane = tid & 31;
    const int gid = lane >> 2, tig = lane & 3;
    const int kw = warp * 16;                  // warp's K16 group within a chunk
    const int bb = tid >> 3;                   // batch row 0..31 (epilogue)
    const int jb = tid & 7;                    // gate sub-col 0..7

    float creg = 0.f;

    for (int t = 0; t < 512; ++t) {
        const __half* hp = &g_hh[t & 1][0][0];

        // Prefetch xproj for this thread (consumed at epilogue)
        const float* xpp = g_xproj + ((size_t)bb * 512 + t) * 4096 + c8 + jb;
        float xp0 = __ldg(xpp);
        float xp1 = __ldg(xpp + 1024);
        float xp2 = __ldg(xpp + 2048);
        float xp3 = __ldg(xpp + 3072);

        // Stage chunk ch (cols [128ch,128ch+128) halves) into stage s.
        // Each thread's 8-half column lies in ONE producer CTA's slice:
        // producer = 16*ch + (tid&15). Poll it, then cp.async (16 B each).
        auto load_h = [&](int s, int ch) {
            if (t > 0) {
                const unsigned* fl = &g_flags[(16 * ch + (tid & 15)) * 32];
                while (ld_acq_gpu(fl) < (unsigned)t) { }
            }
#pragma unroll
            for (int i = tid; i < 512; i += 256) {
                int r = i >> 4, ccc = (i & 15) * 8;
                cp16cg(&sHh[s][r][ccc], hp + (size_t)r * 1024 + ch * 128 + ccc);
            }
            cp_commit();
        };
        load_h(0, chOff & 7);
        load_h(1, (chOff + 1) & 7);
        load_h(2, (chOff + 2) & 7);

        float acc[2][4][4];
#pragma unroll
        for (int mi = 0; mi < 2; ++mi)
#pragma unroll
            for (int ni = 0; ni < 4; ++ni)
#pragma unroll
                for (int r = 0; r < 4; ++r) acc[mi][ni][r] = 0.f;

        for (int p = 0; p < 8; ++p) {
            const int cur = p & 3;
            const int ch = (p + chOff) & 7;    // actual chunk in this slot
            if (p < 6) cp_wait<2>(); else cp_wait<0>();
            __syncthreads();
            if (p < 5) load_h((p + 3) & 3, (p + 3 + chOff) & 7);

            const int kg = ch * 128 + kw;      // global k of this warp's group
            uint32_t af[2][4], bf[4][2];
#pragma unroll
            for (int mi = 0; mi < 2; ++mi) {
                int r = mi * 16 + gid;
                af[mi][0] = *(const uint32_t*)&sHh[cur][r][kw + 2 * tig];
                af[mi][1] = *(const uint32_t*)&sHh[cur][r + 8][kw + 2 * tig];
                af[mi][2] = *(const uint32_t*)&sHh[cur][r][kw + 2 * tig + 8];
                af[mi][3] = *(const uint32_t*)&sHh[cur][r + 8][kw + 2 * tig + 8];
            }
#pragma unroll
            for (int ni = 0; ni < 4; ++ni) {
                int n = ni * 8 + gid;
                bf[ni][0] = *(const uint32_t*)&sWhT[n][kg + 2 * tig];
                bf[ni][1] = *(const uint32_t*)&sWhT[n][kg + 2 * tig + 8];
            }
#pragma unroll
            for (int mi = 0; mi < 2; ++mi)
#pragma unroll
                for (int ni = 0; ni < 4; ++ni)
                    mma_f16(acc[mi][ni], af[mi], bf[ni]);
        }

        __syncthreads();   // all stages consumed; safe to alias partials

#pragma unroll
        for (int mi = 0; mi < 2; ++mi)
#pragma unroll
            for (int ni = 0; ni < 4; ++ni) {
                int r = mi * 16 + gid, c = ni * 8 + tig * 2;
                part[warp][r][c]         = acc[mi][ni][0];
                part[warp][r][c + 1]     = acc[mi][ni][1];
                part[warp][r + 8][c]     = acc[mi][ni][2];
                part[warp][r + 8][c + 1] = acc[mi][ni][3];
            }
        __syncthreads();

        // Reduce partials + xproj -> gates -> cell -> h_t
        float pre[4] = {xp0, xp1, xp2, xp3};
#pragma unroll
        for (int q = 0; q < 4; ++q) {
            int c = q * 8 + jb;
            float s = 0.f;
#pragma unroll
            for (int w = 0; w < 8; ++w) s += part[w][bb][c];
            pre[q] += s;
        }
        float ig = fast_sigmoid(pre[0]);
        float fg = fast_sigmoid(pre[1]);
        float og = fast_sigmoid(pre[2]);
        float gg = fast_tanh(pre[3]);
        creg = fg * creg + ig * gg;
        float hval = og * fast_tanh(creg);
        out[((size_t)bb * 512 + t) * 1024 + c8 + jb] = hval;
        g_hh[(t + 1) & 1][bb][c8 + jb] = __float2half(hval);

        // ---- Publish: fence(release) + flag. Dataflow bounds skew < 1 step,
        //      so overwriting g_hh[(t+1)&1] (h_{t-1}'s slot) is safe. ----
        fence_rel_gpu();
        __syncthreads();
        if (tid == 0) st_rel_gpu(&g_flags[cta * 32], (unsigned)(t + 1));
    }
}

// ----------------------------------------------------------------------------
extern "C" void kernel_launch(void* const* d_in, const int* in_sizes, int n_in,
                              void* d_out, int out_size)
{
    const float* x  = (const float*)d_in[0];   // (32,512,1024)
    const float* h0 = (const float*)d_in[1];   // (32,1024)
    const float* Wx = (const float*)d_in[2];   // (1024,4096)
    const float* Wh = (const float*)d_in[3];   // (1024,4096)
    const float* b  = (const float*)d_in[4];   // (4096,)
    float* out = (float*)d_out;                // (32,512,1024)

    cudaFuncSetAttribute(lstm_persist,
                         cudaFuncAttributeMaxDynamicSharedMemorySize, SMEM_BYTES);

    dim3 gA(32, 128);
    xproj_kernel<<<gA, 256>>>(x, Wx, b);
    init_kernel<<<16, 256>>>(h0);
    lstm_persist<<<128, 256, SMEM_BYTES>>>(Wh, out);
}

// round 10
// speedup vs baseline: 2.2800x; 1.4246x over previous
#include <cuda_runtime.h>
#include <cuda_fp16.h>
#include <cstdint>
#include <cstddef>

// ============================================================================
// LSTM: x (32,512,1024), h0 (32,1024), Wx (1024,4096), Wh (1024,4096), b (4096)
// Phase 1: g_xproj = x @ Wx + b   (tf32 mma.sync, 128x128x16 pipeline)
// Phase 2: ONE persistent kernel, 128 co-resident CTAs, fp16 m16n8k16 mma.
//          Wh resident in SMEM fp16 transposed (66 KB). Per step, the ENTIRE
//          fp16 h (64 KB) is staged in one shot (4096 cp.async, one wait) —
//          one latency exposure instead of 8, no intra-mma syncs.
//          Dataflow sync via per-CTA monotonic flags; h fb via g_hh ping-pong.
// ============================================================================

#define DI __device__ __forceinline__

DI uint32_t smem_u32(const void* p) { return (uint32_t)__cvta_generic_to_shared(p); }

DI void cp16(const void* smem_dst, const void* gsrc) {
    asm volatile("cp.async.ca.shared.global [%0], [%1], 16;"
                 :: "r"(smem_u32(smem_dst)), "l"(gsrc));
}
DI void cp16cg(const void* smem_dst, const void* gsrc) {
    asm volatile("cp.async.cg.shared.global [%0], [%1], 16;"
                 :: "r"(smem_u32(smem_dst)), "l"(gsrc));
}
DI void cp_commit() { asm volatile("cp.async.commit_group;"); }
template<int N> DI void cp_wait() { asm volatile("cp.async.wait_group %0;" :: "n"(N)); }

DI uint32_t f2tf32(float f) {
    uint32_t u;
    asm("cvt.rna.tf32.f32 %0, %1;" : "=r"(u) : "f"(f));
    return u;
}

DI unsigned ld_acq_gpu(const unsigned* p) {
    unsigned v;
    asm volatile("ld.acquire.gpu.u32 %0, [%1];" : "=r"(v) : "l"(p));
    return v;
}
DI void st_rel_gpu(unsigned* p, unsigned v) {
    asm volatile("st.release.gpu.u32 [%0], %1;" :: "l"(p), "r"(v) : "memory");
}

DI void mma_tf32(float* c, const uint32_t* a, const uint32_t* b) {
    asm volatile(
        "mma.sync.aligned.m16n8k8.row.col.f32.tf32.tf32.f32 "
        "{%0,%1,%2,%3}, {%4,%5,%6,%7}, {%8,%9}, {%0,%1,%2,%3};"
        : "+f"(c[0]), "+f"(c[1]), "+f"(c[2]), "+f"(c[3])
        : "r"(a[0]), "r"(a[1]), "r"(a[2]), "r"(a[3]), "r"(b[0]), "r"(b[1]));
}

DI void mma_f16(float* c, const uint32_t* a, const uint32_t* b) {
    asm volatile(
        "mma.sync.aligned.m16n8k16.row.col.f32.f16.f16.f32 "
        "{%0,%1,%2,%3}, {%4,%5,%6,%7}, {%8,%9}, {%0,%1,%2,%3};"
        : "+f"(c[0]), "+f"(c[1]), "+f"(c[2]), "+f"(c[3])
        : "r"(a[0]), "r"(a[1]), "r"(a[2]), "r"(a[3]), "r"(b[0]), "r"(b[1]));
}

DI float fast_sigmoid(float x) { return 1.f / (1.f + __expf(-x)); }
DI float fast_tanh(float x) {
    float e = __expf(-2.f * x);
    return (1.f - e) / (1.f + e);
}

// Scratch (allocation-free rule: __device__ globals)
__device__ float g_xproj[16384 * 4096];      // 256 MB: (N*T, 4H)
__device__ __half g_hh[2][32][1024];         // fp16 h, ping-pong by t parity
__device__ unsigned g_flags[128 * 32];       // per-CTA completed-step counters

// ----------------------------------------------------------------------------
// Phase 1: xproj = X(16384x1024) @ Wx(1024x4096) + b  (unchanged, tf32)
// ----------------------------------------------------------------------------
__global__ void __launch_bounds__(256) xproj_kernel(
    const float* __restrict__ X, const float* __restrict__ Wx,
    const float* __restrict__ bias)
{
    __shared__ float sA[2][128][20];
    __shared__ float sB[2][16][136];

    const int tid   = threadIdx.x;
    const int mBase = blockIdx.y * 128;
    const int nBase = blockIdx.x * 128;

    auto load_stage = [&](int s, int k0) {
#pragma unroll
        for (int i = tid; i < 512; i += 256) {
            int r = i >> 2, c = (i & 3) << 2;
            cp16(&sA[s][r][c], X + (size_t)(mBase + r) * 1024 + k0 + c);
        }
#pragma unroll
        for (int i = tid; i < 512; i += 256) {
            int r = i >> 5, c = (i & 31) << 2;
            cp16(&sB[s][r][c], Wx + (size_t)(k0 + r) * 4096 + nBase + c);
        }
        cp_commit();
    };

    load_stage(0, 0);

    const int warp = tid >> 5, lane = tid & 31;
    const int wm = (warp >> 2) * 64, wn = (warp & 3) * 32;
    const int gid = lane >> 2, tig = lane & 3;

    float acc[4][4][4];
#pragma unroll
    for (int mi = 0; mi < 4; ++mi)
#pragma unroll
        for (int ni = 0; ni < 4; ++ni)
#pragma unroll
            for (int r = 0; r < 4; ++r) acc[mi][ni][r] = 0.f;

    for (int kt = 0; kt < 64; ++kt) {
        const int cur = kt & 1;
        cp_wait<0>();
        __syncthreads();
        if (kt < 63) load_stage(cur ^ 1, (kt + 1) * 16);

#pragma unroll
        for (int kk = 0; kk < 16; kk += 8) {
            uint32_t af[4][4], bf[4][2];
#pragma unroll
            for (int mi = 0; mi < 4; ++mi) {
                int r = wm + mi * 16 + gid;
                af[mi][0] = f2tf32(sA[cur][r][kk + tig]);
                af[mi][1] = f2tf32(sA[cur][r + 8][kk + tig]);
                af[mi][2] = f2tf32(sA[cur][r][kk + tig + 4]);
                af[mi][3] = f2tf32(sA[cur][r + 8][kk + tig + 4]);
            }
#pragma unroll
            for (int ni = 0; ni < 4; ++ni) {
                int cc = wn + ni * 8 + gid;
                bf[ni][0] = f2tf32(sB[cur][kk + tig][cc]);
                bf[ni][1] = f2tf32(sB[cur][kk + tig + 4][cc]);
            }
#pragma unroll
            for (int mi = 0; mi < 4; ++mi)
#pragma unroll
                for (int ni = 0; ni < 4; ++ni)
                    mma_tf32(acc[mi][ni], af[mi], bf[ni]);
        }
    }

#pragma unroll
    for (int mi = 0; mi < 4; ++mi) {
#pragma unroll
        for (int ni = 0; ni < 4; ++ni) {
            int row = mBase + wm + mi * 16 + gid;
            int col = nBase + wn + ni * 8 + tig * 2;
            float b0 = bias[col], b1 = bias[col + 1];
            float* p0 = g_xproj + (size_t)row * 4096 + col;
            p0[0] = acc[mi][ni][0] + b0;
            p0[1] = acc[mi][ni][1] + b1;
            float* p1 = g_xproj + (size_t)(row + 8) * 4096 + col;
            p1[0] = acc[mi][ni][2] + b0;
            p1[1] = acc[mi][ni][3] + b1;
        }
    }
}

// ----------------------------------------------------------------------------
// init: clear flags; seed g_hh[0] = fp16(h0)
// ----------------------------------------------------------------------------
__global__ void init_kernel(const float* __restrict__ h0) {
    int i = blockIdx.x * 256 + threadIdx.x;          // 4096 threads
    if (i < 128 * 32) g_flags[i] = 0u;
    for (int idx = i; idx < 32 * 1024; idx += 4096)
        g_hh[0][idx >> 10][idx & 1023] = __float2half(h0[idx]);
}

// ----------------------------------------------------------------------------
// Phase 2: persistent recurrence, fp16 mma, one-shot h staging.
// SMEM (dynamic, 132096 B):
//   [0, 66048)        sWhT: fp16 Wh^T [32 n][1032 k]  (stride 516 words)
//   [66048, 132096)   sHh: fp16 h [32 b][1032 k]      (stride 516 words);
//                     partials 8x32x40 fp32 alias this after mma.
// Warp w owns k-range [w*128, w*128+128): 8 sub-iters, 16 LDS + 8 mma each,
// no syncs inside. bank = 4*gid + tig (+4r, r≡ mod 8) -> conflict-free.
// ----------------------------------------------------------------------------
static const int ROW_HALVES = 1032;                        // halves per row
static const int SWHT_BYTES = 32 * ROW_HALVES * 2;         // 66048
static const int SMEM_BYTES = 2 * SWHT_BYTES;              // 132096

__global__ void __launch_bounds__(256, 1) lstm_persist(
    const float* __restrict__ Wh, float* __restrict__ out)
{
    extern __shared__ __align__(16) char dyn[];
    __half (*sWhT)[ROW_HALVES] = reinterpret_cast<__half (*)[ROW_HALVES]>(dyn);
    __half (*sHh)[ROW_HALVES]  = reinterpret_cast<__half (*)[ROW_HALVES]>(dyn + SWHT_BYTES);
    float (*part)[32][40] = reinterpret_cast<float (*)[32][40]>(dyn + SWHT_BYTES);

    const int tid = threadIdx.x;
    const int cta = blockIdx.x;
    const int c8  = cta * 8;

    // One-time: resident Wh slice as fp16, transposed [n][k].
    for (int idx = tid; idx < 32 * 1024; idx += 256) {
        int k = idx >> 5, col = idx & 31;
        int q = col >> 3, jj = col & 7;
        sWhT[col][k] = __float2half(Wh[(size_t)k * 4096 + q * 1024 + c8 + jj]);
    }
    __syncthreads();

    const int warp = tid >> 5, lane = tid & 31;
    const int gid = lane >> 2, tig = lane & 3;
    const int kw = warp * 128;                 // warp's k-range (halves)
    const int bb = tid >> 3;                   // batch row 0..31 (epilogue)
    const int jb = tid & 7;                    // gate sub-col 0..7
    const int mycol8 = (tid & 127) * 8;        // this thread's 8-half h column

    float creg = 0.f;

    for (int t = 0; t < 512; ++t) {
        const __half* hp = &g_hh[t & 1][0][0];

        // Prefetch xproj for this thread (DRAM; consumed at epilogue)
        const float* xpp = g_xproj + ((size_t)bb * 512 + t) * 4096 + c8 + jb;
        float xp0 = __ldg(xpp);
        float xp1 = __ldg(xpp + 1024);
        float xp2 = __ldg(xpp + 2048);
        float xp3 = __ldg(xpp + 3072);

        // ---- Wait for ALL producers of h_{t-1}, then stage all of h ----
        if (t > 0) {
            if (tid < 128) {
                while (ld_acq_gpu(&g_flags[tid * 32]) < (unsigned)t) { }
            }
            __syncthreads();
        }
        // 4096 x 16B copies: thread covers rows {2k + (tid>>7)}, fixed col slice
#pragma unroll
        for (int k = 0; k < 16; ++k) {
            int r = 2 * k + (tid >> 7);
            cp16cg(&sHh[r][mycol8], hp + (size_t)r * 1024 + mycol8);
        }
        cp_commit();
        cp_wait<0>();
        __syncthreads();

        // ---- Full split-K mma, no internal syncs, full ILP ----
        float acc[2][4][4];
#pragma unroll
        for (int mi = 0; mi < 2; ++mi)
#pragma unroll
            for (int ni = 0; ni < 4; ++ni)
#pragma unroll
                for (int r = 0; r < 4; ++r) acc[mi][ni][r] = 0.f;

#pragma unroll
        for (int sub = 0; sub < 8; ++sub) {
            const int kg = kw + sub * 16;
            uint32_t af[2][4], bf[4][2];
#pragma unroll
            for (int mi = 0; mi < 2; ++mi) {
                int r = mi * 16 + gid;
                af[mi][0] = *(const uint32_t*)&sHh[r][kg + 2 * tig];
                af[mi][1] = *(const uint32_t*)&sHh[r + 8][kg + 2 * tig];
                af[mi][2] = *(const uint32_t*)&sHh[r][kg + 2 * tig + 8];
                af[mi][3] = *(const uint32_t*)&sHh[r + 8][kg + 2 * tig + 8];
            }
#pragma unroll
            for (int ni = 0; ni < 4; ++ni) {
                int n = ni * 8 + gid;
                bf[ni][0] = *(const uint32_t*)&sWhT[n][kg + 2 * tig];
                bf[ni][1] = *(const uint32_t*)&sWhT[n][kg + 2 * tig + 8];
            }
#pragma unroll
            for (int mi = 0; mi < 2; ++mi)
#pragma unroll
                for (int ni = 0; ni < 4; ++ni)
                    mma_f16(acc[mi][ni], af[mi], bf[ni]);
        }

        __syncthreads();   // sHh consumed; safe to alias partials

#pragma unroll
        for (int mi = 0; mi < 2; ++mi)
#pragma unroll
            for (int ni = 0; ni < 4; ++ni) {
                int r = mi * 16 + gid, c = ni * 8 + tig * 2;
                part[warp][r][c]         = acc[mi][ni][0];
                part[warp][r][c + 1]     = acc[mi][ni][1];
                part[warp][r + 8][c]     = acc[mi][ni][2];
                part[warp][r + 8][c + 1] = acc[mi][ni][3];
            }
        __syncthreads();

        // Reduce partials + xproj -> gates -> cell -> h_t (coalesced stores)
        float pre[4] = {xp0, xp1, xp2, xp3};
#pragma unroll
        for (int q = 0; q < 4; ++q) {
            int c = q * 8 + jb;
            float s = 0.f;
#pragma unroll
            for (int w = 0; w < 8; ++w) s += part[w][bb][c];
            pre[q] += s;
        }
        float ig = fast_sigmoid(pre[0]);
        float fg = fast_sigmoid(pre[1]);
        float og = fast_sigmoid(pre[2]);
        float gg = fast_tanh(pre[3]);
        creg = fg * creg + ig * gg;
        float hval = og * fast_tanh(creg);
        g_hh[(t + 1) & 1][bb][c8 + jb] = __float2half(hval);
        out[((size_t)bb * 512 + t) * 1024 + c8 + jb] = hval;

        // ---- Publish: bar orders all threads' stores before the release ----
        __syncthreads();
        if (tid == 0) st_rel_gpu(&g_flags[cta * 32], (unsigned)(t + 1));
    }
}

// ----------------------------------------------------------------------------
extern "C" void kernel_launch(void* const* d_in, const int* in_sizes, int n_in,
                              void* d_out, int out_size)
{
    const float* x  = (const float*)d_in[0];   // (32,512,1024)
    const float* h0 = (const float*)d_in[1];   // (32,1024)
    const float* Wx = (const float*)d_in[2];   // (1024,4096)
    const float* Wh = (const float*)d_in[3];   // (1024,4096)
    const float* b  = (const float*)d_in[4];   // (4096,)
    float* out = (float*)d_out;                // (32,512,1024)

    cudaFuncSetAttribute(lstm_persist,
                         cudaFuncAttributeMaxDynamicSharedMemorySize, SMEM_BYTES);

    dim3 gA(32, 128);
    xproj_kernel<<<gA, 256>>>(x, Wx, b);
    init_kernel<<<16, 256>>>(h0);
    lstm_persist<<<128, 256, SMEM_BYTES>>>(Wh, out);
}

// round 11
// speedup vs baseline: 2.6497x; 1.1622x over previous
#include <cuda_runtime.h>
#include <cuda_fp16.h>
#include <cstdint>
#include <cstddef>

// ============================================================================
// LSTM: x (32,512,1024), h0 (32,1024), Wx (1024,4096), Wh (1024,4096), b (4096)
// Phase 0: convert X -> fp16 (same layout), Wx -> fp16 transposed [n][k].
// Phase 1: g_xproj = x @ Wx + b   (fp16 m16n8k16 mma, no in-loop cvt)
// Phase 2: ONE persistent kernel, 128 co-resident CTAs, fp16 m16n8k16 mma.
//          Wh resident in SMEM fp16 transposed (66 KB). Whole fp16 h (64 KB)
//          staged per step in one shot; per-THREAD producer-flag poll before
//          each thread's own cp.asyncs (no all-producer gate).
// ============================================================================

#define DI __device__ __forceinline__

DI uint32_t smem_u32(const void* p) { return (uint32_t)__cvta_generic_to_shared(p); }

DI void cp16cg(const void* smem_dst, const void* gsrc) {
    asm volatile("cp.async.cg.shared.global [%0], [%1], 16;"
                 :: "r"(smem_u32(smem_dst)), "l"(gsrc));
}
DI void cp_commit() { asm volatile("cp.async.commit_group;"); }
template<int N> DI void cp_wait() { asm volatile("cp.async.wait_group %0;" :: "n"(N)); }

DI unsigned ld_acq_gpu(const unsigned* p) {
    unsigned v;
    asm volatile("ld.acquire.gpu.u32 %0, [%1];" : "=r"(v) : "l"(p));
    return v;
}
DI void st_rel_gpu(unsigned* p, unsigned v) {
    asm volatile("st.release.gpu.u32 [%0], %1;" :: "l"(p), "r"(v) : "memory");
}

DI void mma_f16(float* c, const uint32_t* a, const uint32_t* b) {
    asm volatile(
        "mma.sync.aligned.m16n8k16.row.col.f32.f16.f16.f32 "
        "{%0,%1,%2,%3}, {%4,%5,%6,%7}, {%8,%9}, {%0,%1,%2,%3};"
        : "+f"(c[0]), "+f"(c[1]), "+f"(c[2]), "+f"(c[3])
        : "r"(a[0]), "r"(a[1]), "r"(a[2]), "r"(a[3]), "r"(b[0]), "r"(b[1]));
}

DI float fast_sigmoid(float x) { return 1.f / (1.f + __expf(-x)); }
DI float fast_tanh(float x) {
    float e = __expf(-2.f * x);
    return (1.f - e) / (1.f + e);
}

// Scratch (allocation-free rule: __device__ globals)
__device__ float g_xproj[16384 * 4096];      // 256 MB: (N*T, 4H)
__device__ __half g_x16[16384 * 1024];       // 32 MB: fp16 X
__device__ __half g_wxT16[4096 * 1024];      // 8 MB: fp16 Wx^T [n][k]
__device__ __half g_hh[2][32][1024];         // fp16 h, ping-pong by t parity
__device__ unsigned g_flags[128 * 32];       // per-CTA completed-step counters

// ----------------------------------------------------------------------------
// Phase 0a: X -> fp16 (same layout). 8 elems/thread.
// ----------------------------------------------------------------------------
__global__ void conv_x(const float* __restrict__ X) {
    size_t i = ((size_t)blockIdx.x * 256 + threadIdx.x) * 8;
    float4 a = *(const float4*)(X + i);
    float4 b = *(const float4*)(X + i + 4);
    __half2 h[4];
    h[0] = __floats2half2_rn(a.x, a.y);
    h[1] = __floats2half2_rn(a.z, a.w);
    h[2] = __floats2half2_rn(b.x, b.y);
    h[3] = __floats2half2_rn(b.z, b.w);
    *(uint4*)(g_x16 + i) = *(const uint4*)h;
}

// ----------------------------------------------------------------------------
// Phase 0b: Wx [k][n] -> fp16 transposed [n][k]. 32x32 smem tiles.
// grid (32 k-tiles, 128 n-tiles), block 256 (32x8).
// ----------------------------------------------------------------------------
__global__ void conv_wt(const float* __restrict__ Wx) {
    __shared__ float tile[32][33];
    const int tx = threadIdx.x & 31, ty = threadIdx.x >> 5;
    const int kBase = blockIdx.x * 32;
    const int nBase = blockIdx.y * 32;
#pragma unroll
    for (int r = 0; r < 32; r += 8)
        tile[ty + r][tx] = Wx[(size_t)(kBase + ty + r) * 4096 + nBase + tx];
    __syncthreads();
#pragma unroll
    for (int r = 0; r < 32; r += 8)
        g_wxT16[(size_t)(nBase + ty + r) * 1024 + kBase + tx] =
            __float2half(tile[tx][ty + r]);
}

// ----------------------------------------------------------------------------
// Phase 1: xproj = X16(16384x1024) @ WxT16 + b, fp16 m16n8k16.
// Tile 128x128, BK=32 halves, double-buffered. 8 warps, warp tile 64x32.
// sA [m][k], sB [n][k], both stride 40 halves (conflict-free: 20*gid+tig).
// ----------------------------------------------------------------------------
__global__ void __launch_bounds__(256) xproj16_kernel(
    const float* __restrict__ bias)
{
    __shared__ __half sA[2][128][40];
    __shared__ __half sB[2][128][40];

    const int tid   = threadIdx.x;
    const int mBase = blockIdx.y * 128;
    const int nBase = blockIdx.x * 128;

    auto load_stage = [&](int s, int k0) {
#pragma unroll
        for (int i = tid; i < 512; i += 256) {
            int r = i >> 2, c8 = (i & 3) * 8;
            cp16cg(&sA[s][r][c8], g_x16 + (size_t)(mBase + r) * 1024 + k0 + c8);
        }
#pragma unroll
        for (int i = tid; i < 512; i += 256) {
            int r = i >> 2, c8 = (i & 3) * 8;
            cp16cg(&sB[s][r][c8], g_wxT16 + (size_t)(nBase + r) * 1024 + k0 + c8);
        }
        cp_commit();
    };

    load_stage(0, 0);

    const int warp = tid >> 5, lane = tid & 31;
    const int wm = (warp >> 2) * 64, wn = (warp & 3) * 32;
    const int gid = lane >> 2, tig = lane & 3;

    float acc[4][4][4];
#pragma unroll
    for (int mi = 0; mi < 4; ++mi)
#pragma unroll
        for (int ni = 0; ni < 4; ++ni)
#pragma unroll
            for (int r = 0; r < 4; ++r) acc[mi][ni][r] = 0.f;

    for (int kt = 0; kt < 32; ++kt) {
        const int cur = kt & 1;
        cp_wait<0>();
        __syncthreads();
        if (kt < 31) load_stage(cur ^ 1, (kt + 1) * 32);

#pragma unroll
        for (int ks = 0; ks < 32; ks += 16) {
            uint32_t af[4][4], bf[4][2];
#pragma unroll
            for (int mi = 0; mi < 4; ++mi) {
                int r = wm + mi * 16 + gid;
                af[mi][0] = *(const uint32_t*)&sA[cur][r][ks + 2 * tig];
                af[mi][1] = *(const uint32_t*)&sA[cur][r + 8][ks + 2 * tig];
                af[mi][2] = *(const uint32_t*)&sA[cur][r][ks + 2 * tig + 8];
                af[mi][3] = *(const uint32_t*)&sA[cur][r + 8][ks + 2 * tig + 8];
            }
#pragma unroll
            for (int ni = 0; ni < 4; ++ni) {
                int n = wn + ni * 8 + gid;
                bf[ni][0] = *(const uint32_t*)&sB[cur][n][ks + 2 * tig];
                bf[ni][1] = *(const uint32_t*)&sB[cur][n][ks + 2 * tig + 8];
            }
#pragma unroll
            for (int mi = 0; mi < 4; ++mi)
#pragma unroll
                for (int ni = 0; ni < 4; ++ni)
                    mma_f16(acc[mi][ni], af[mi], bf[ni]);
        }
    }

#pragma unroll
    for (int mi = 0; mi < 4; ++mi) {
#pragma unroll
        for (int ni = 0; ni < 4; ++ni) {
            int row = mBase + wm + mi * 16 + gid;
            int col = nBase + wn + ni * 8 + tig * 2;
            float b0 = bias[col], b1 = bias[col + 1];
            float* p0 = g_xproj + (size_t)row * 4096 + col;
            p0[0] = acc[mi][ni][0] + b0;
            p0[1] = acc[mi][ni][1] + b1;
            float* p1 = g_xproj + (size_t)(row + 8) * 4096 + col;
            p1[0] = acc[mi][ni][2] + b0;
            p1[1] = acc[mi][ni][3] + b1;
        }
    }
}

// ----------------------------------------------------------------------------
// init: clear flags; seed g_hh[0] = fp16(h0)
// ----------------------------------------------------------------------------
__global__ void init_kernel(const float* __restrict__ h0) {
    int i = blockIdx.x * 256 + threadIdx.x;          // 4096 threads
    if (i < 128 * 32) g_flags[i] = 0u;
    for (int idx = i; idx < 32 * 1024; idx += 4096)
        g_hh[0][idx >> 10][idx & 1023] = __float2half(h0[idx]);
}

// ----------------------------------------------------------------------------
// Phase 2: persistent recurrence (R10 skeleton + per-thread producer poll).
// SMEM (dynamic, 132096 B):
//   [0, 66048)        sWhT: fp16 Wh^T [32 n][1032 k]
//   [66048, 132096)   sHh: fp16 h [32 b][1032 k]; partials 8x32x40 alias after.
// ----------------------------------------------------------------------------
static const int ROW_HALVES = 1032;
static const int SWHT_BYTES = 32 * ROW_HALVES * 2;         // 66048
static const int SMEM_BYTES = 2 * SWHT_BYTES;              // 132096

__global__ void __launch_bounds__(256, 1) lstm_persist(
    const float* __restrict__ Wh, float* __restrict__ out)
{
    extern __shared__ __align__(16) char dyn[];
    __half (*sWhT)[ROW_HALVES] = reinterpret_cast<__half (*)[ROW_HALVES]>(dyn);
    __half (*sHh)[ROW_HALVES]  = reinterpret_cast<__half (*)[ROW_HALVES]>(dyn + SWHT_BYTES);
    float (*part)[32][40] = reinterpret_cast<float (*)[32][40]>(dyn + SWHT_BYTES);

    const int tid = threadIdx.x;
    const int cta = blockIdx.x;
    const int c8  = cta * 8;

    // One-time: resident Wh slice as fp16, transposed [n][k].
    for (int idx = tid; idx < 32 * 1024; idx += 256) {
        int k = idx >> 5, col = idx & 31;
        int q = col >> 3, jj = col & 7;
        sWhT[col][k] = __float2half(Wh[(size_t)k * 4096 + q * 1024 + c8 + jj]);
    }
    __syncthreads();

    const int warp = tid >> 5, lane = tid & 31;
    const int gid = lane >> 2, tig = lane & 3;
    const int kw = warp * 128;                 // warp's k-range (halves)
    const int bb = tid >> 3;                   // batch row 0..31 (epilogue)
    const int jb = tid & 7;                    // gate sub-col 0..7
    const int mycol8 = (tid & 127) * 8;        // this thread's 8-half h column
    const unsigned* myfl = &g_flags[(tid & 127) * 32];   // its single producer

    float creg = 0.f;

    for (int t = 0; t < 512; ++t) {
        const __half* hp = &g_hh[t & 1][0][0];

        // Prefetch xproj for this thread (DRAM; consumed at epilogue)
        const float* xpp = g_xproj + ((size_t)bb * 512 + t) * 4096 + c8 + jb;
        float xp0 = __ldg(xpp);
        float xp1 = __ldg(xpp + 1024);
        float xp2 = __ldg(xpp + 2048);
        float xp3 = __ldg(xpp + 3072);

        // ---- Per-thread producer poll, then stage this thread's h columns ----
        if (t > 0) {
            while (ld_acq_gpu(myfl) < (unsigned)t) { }
        }
#pragma unroll
        for (int k = 0; k < 16; ++k) {
            int r = 2 * k + (tid >> 7);
            cp16cg(&sHh[r][mycol8], hp + (size_t)r * 1024 + mycol8);
        }
        cp_commit();
        cp_wait<0>();
        __syncthreads();

        // ---- Full split-K mma, no internal syncs ----
        float acc[2][4][4];
#pragma unroll
        for (int mi = 0; mi < 2; ++mi)
#pragma unroll
            for (int ni = 0; ni < 4; ++ni)
#pragma unroll
                for (int r = 0; r < 4; ++r) acc[mi][ni][r] = 0.f;

#pragma unroll
        for (int sub = 0; sub < 8; ++sub) {
            const int kg = kw + sub * 16;
            uint32_t af[2][4], bf[4][2];
#pragma unroll
            for (int mi = 0; mi < 2; ++mi) {
                int r = mi * 16 + gid;
                af[mi][0] = *(const uint32_t*)&sHh[r][kg + 2 * tig];
                af[mi][1] = *(const uint32_t*)&sHh[r + 8][kg + 2 * tig];
                af[mi][2] = *(const uint32_t*)&sHh[r][kg + 2 * tig + 8];
                af[mi][3] = *(const uint32_t*)&sHh[r + 8][kg + 2 * tig + 8];
            }
#pragma unroll
            for (int ni = 0; ni < 4; ++ni) {
                int n = ni * 8 + gid;
                bf[ni][0] = *(const uint32_t*)&sWhT[n][kg + 2 * tig];
                bf[ni][1] = *(const uint32_t*)&sWhT[n][kg + 2 * tig + 8];
            }
#pragma unroll
            for (int mi = 0; mi < 2; ++mi)
#pragma unroll
                for (int ni = 0; ni < 4; ++ni)
                    mma_f16(acc[mi][ni], af[mi], bf[ni]);
        }

        __syncthreads();   // sHh consumed; safe to alias partials

#pragma unroll
        for (int mi = 0; mi < 2; ++mi)
#pragma unroll
            for (int ni = 0; ni < 4; ++ni) {
                int r = mi * 16 + gid, c = ni * 8 + tig * 2;
                part[warp][r][c]         = acc[mi][ni][0];
                part[warp][r][c + 1]     = acc[mi][ni][1];
                part[warp][r + 8][c]     = acc[mi][ni][2];
                part[warp][r + 8][c + 1] = acc[mi][ni][3];
            }
        __syncthreads();

        // Reduce partials + xproj -> gates -> cell -> h_t (coalesced stores)
        float pre[4] = {xp0, xp1, xp2, xp3};
#pragma unroll
        for (int q = 0; q < 4; ++q) {
            int c = q * 8 + jb;
            float s = 0.f;
#pragma unroll
            for (int w = 0; w < 8; ++w) s += part[w][bb][c];
            pre[q] += s;
        }
        float ig = fast_sigmoid(pre[0]);
        float fg = fast_sigmoid(pre[1]);
        float og = fast_sigmoid(pre[2]);
        float gg = fast_tanh(pre[3]);
        creg = fg * creg + ig * gg;
        float hval = og * fast_tanh(creg);
        g_hh[(t + 1) & 1][bb][c8 + jb] = __float2half(hval);
        out[((size_t)bb * 512 + t) * 1024 + c8 + jb] = hval;

        // ---- Publish: bar orders all threads' stores before the release ----
        __syncthreads();
        if (tid == 0) st_rel_gpu(&g_flags[cta * 32], (unsigned)(t + 1));
    }
}

// ----------------------------------------------------------------------------
extern "C" void kernel_launch(void* const* d_in, const int* in_sizes, int n_in,
                              void* d_out, int out_size)
{
    const float* x  = (const float*)d_in[0];   // (32,512,1024)
    const float* h0 = (const float*)d_in[1];   // (32,1024)
    const float* Wx = (const float*)d_in[2];   // (1024,4096)
    const float* Wh = (const float*)d_in[3];   // (1024,4096)
    const float* b  = (const float*)d_in[4];   // (4096,)
    float* out = (float*)d_out;                // (32,512,1024)

    cudaFuncSetAttribute(lstm_persist,
                         cudaFuncAttributeMaxDynamicSharedMemorySize, SMEM_BYTES);

    conv_x<<<8192, 256>>>(x);
    conv_wt<<<dim3(32, 128), 256>>>(Wx);
    init_kernel<<<16, 256>>>(h0);

    dim3 gA(32, 128);                          // n-tiles x m-tiles
    xproj16_kernel<<<gA, 256>>>(b);
    lstm_persist<<<128, 256, SMEM_BYTES>>>(Wh, out);
}

// round 12
// speedup vs baseline: 2.7035x; 1.0203x over previous
#include <cuda_runtime.h>
#include <cuda_fp16.h>
#include <cstdint>
#include <cstddef>

// ============================================================================
// LSTM: x (32,512,1024), h0 (32,1024), Wx (1024,4096), Wh (1024,4096), b (4096)
// Phase 0: X -> fp16; Wx -> fp16 transposed [n][k].
// Phase 1: g_xproj = x @ Wx + b   (fp16 m16n8k16)
// Phase 2: persistent recurrence, 128 CTAs. PER-WARP dataflow: warp w stages
//          and consumes only h cols [128w,128w+128); its lanes poll only its
//          own 16 producer CTAs; cp.async groups are per-thread so the warp
//          enters mma as soon as ITS data is in — no block-wide staging gate.
//          Only 2 __syncthreads/step (around the cross-warp reduce).
// ============================================================================

#define DI __device__ __forceinline__

DI uint32_t smem_u32(const void* p) { return (uint32_t)__cvta_generic_to_shared(p); }

DI void cp16cg(const void* smem_dst, const void* gsrc) {
    asm volatile("cp.async.cg.shared.global [%0], [%1], 16;"
                 :: "r"(smem_u32(smem_dst)), "l"(gsrc));
}
DI void cp_commit() { asm volatile("cp.async.commit_group;"); }
template<int N> DI void cp_wait() { asm volatile("cp.async.wait_group %0;" :: "n"(N)); }

DI unsigned ld_acq_gpu(const unsigned* p) {
    unsigned v;
    asm volatile("ld.acquire.gpu.u32 %0, [%1];" : "=r"(v) : "l"(p));
    return v;
}
DI void st_rel_gpu(unsigned* p, unsigned v) {
    asm volatile("st.release.gpu.u32 [%0], %1;" :: "l"(p), "r"(v) : "memory");
}

DI void mma_f16(float* c, const uint32_t* a, const uint32_t* b) {
    asm volatile(
        "mma.sync.aligned.m16n8k16.row.col.f32.f16.f16.f32 "
        "{%0,%1,%2,%3}, {%4,%5,%6,%7}, {%8,%9}, {%0,%1,%2,%3};"
        : "+f"(c[0]), "+f"(c[1]), "+f"(c[2]), "+f"(c[3])
        : "r"(a[0]), "r"(a[1]), "r"(a[2]), "r"(a[3]), "r"(b[0]), "r"(b[1]));
}

DI float fast_sigmoid(float x) { return 1.f / (1.f + __expf(-x)); }
DI float fast_tanh(float x) {
    float e = __expf(-2.f * x);
    return (1.f - e) / (1.f + e);
}

// Scratch (allocation-free rule: __device__ globals)
__device__ float g_xproj[16384 * 4096];      // 256 MB: (N*T, 4H)
__device__ __half g_x16[16384 * 1024];       // 32 MB: fp16 X
__device__ __half g_wxT16[4096 * 1024];      // 8 MB: fp16 Wx^T [n][k]
__device__ __half g_hh[2][32][1024];         // fp16 h, ping-pong by t parity
__device__ unsigned g_flags[128 * 32];       // per-CTA completed-step counters

// ----------------------------------------------------------------------------
// Phase 0a: X -> fp16 (same layout). 8 elems/thread.
// ----------------------------------------------------------------------------
__global__ void conv_x(const float* __restrict__ X) {
    size_t i = ((size_t)blockIdx.x * 256 + threadIdx.x) * 8;
    float4 a = *(const float4*)(X + i);
    float4 b = *(const float4*)(X + i + 4);
    __half2 h[4];
    h[0] = __floats2half2_rn(a.x, a.y);
    h[1] = __floats2half2_rn(a.z, a.w);
    h[2] = __floats2half2_rn(b.x, b.y);
    h[3] = __floats2half2_rn(b.z, b.w);
    *(uint4*)(g_x16 + i) = *(const uint4*)h;
}

// ----------------------------------------------------------------------------
// Phase 0b: Wx [k][n] -> fp16 transposed [n][k]. 32x32 smem tiles.
// ----------------------------------------------------------------------------
__global__ void conv_wt(const float* __restrict__ Wx) {
    __shared__ float tile[32][33];
    const int tx = threadIdx.x & 31, ty = threadIdx.x >> 5;
    const int kBase = blockIdx.x * 32;
    const int nBase = blockIdx.y * 32;
#pragma unroll
    for (int r = 0; r < 32; r += 8)
        tile[ty + r][tx] = Wx[(size_t)(kBase + ty + r) * 4096 + nBase + tx];
    __syncthreads();
#pragma unroll
    for (int r = 0; r < 32; r += 8)
        g_wxT16[(size_t)(nBase + ty + r) * 1024 + kBase + tx] =
            __float2half(tile[tx][ty + r]);
}

// ----------------------------------------------------------------------------
// Phase 1: xproj = X16(16384x1024) @ WxT16 + b, fp16 m16n8k16. (as R11)
// ----------------------------------------------------------------------------
__global__ void __launch_bounds__(256) xproj16_kernel(
    const float* __restrict__ bias)
{
    __shared__ __half sA[2][128][40];
    __shared__ __half sB[2][128][40];

    const int tid   = threadIdx.x;
    const int mBase = blockIdx.y * 128;
    const int nBase = blockIdx.x * 128;

    auto load_stage = [&](int s, int k0) {
#pragma unroll
        for (int i = tid; i < 512; i += 256) {
            int r = i >> 2, c8 = (i & 3) * 8;
            cp16cg(&sA[s][r][c8], g_x16 + (size_t)(mBase + r) * 1024 + k0 + c8);
        }
#pragma unroll
        for (int i = tid; i < 512; i += 256) {
            int r = i >> 2, c8 = (i & 3) * 8;
            cp16cg(&sB[s][r][c8], g_wxT16 + (size_t)(nBase + r) * 1024 + k0 + c8);
        }
        cp_commit();
    };

    load_stage(0, 0);

    const int warp = tid >> 5, lane = tid & 31;
    const int wm = (warp >> 2) * 64, wn = (warp & 3) * 32;
    const int gid = lane >> 2, tig = lane & 3;

    float acc[4][4][4];
#pragma unroll
    for (int mi = 0; mi < 4; ++mi)
#pragma unroll
        for (int ni = 0; ni < 4; ++ni)
#pragma unroll
            for (int r = 0; r < 4; ++r) acc[mi][ni][r] = 0.f;

    for (int kt = 0; kt < 32; ++kt) {
        const int cur = kt & 1;
        cp_wait<0>();
        __syncthreads();
        if (kt < 31) load_stage(cur ^ 1, (kt + 1) * 32);

#pragma unroll
        for (int ks = 0; ks < 32; ks += 16) {
            uint32_t af[4][4], bf[4][2];
#pragma unroll
            for (int mi = 0; mi < 4; ++mi) {
                int r = wm + mi * 16 + gid;
                af[mi][0] = *(const uint32_t*)&sA[cur][r][ks + 2 * tig];
                af[mi][1] = *(const uint32_t*)&sA[cur][r + 8][ks + 2 * tig];
                af[mi][2] = *(const uint32_t*)&sA[cur][r][ks + 2 * tig + 8];
                af[mi][3] = *(const uint32_t*)&sA[cur][r + 8][ks + 2 * tig + 8];
            }
#pragma unroll
            for (int ni = 0; ni < 4; ++ni) {
                int n = wn + ni * 8 + gid;
                bf[ni][0] = *(const uint32_t*)&sB[cur][n][ks + 2 * tig];
                bf[ni][1] = *(const uint32_t*)&sB[cur][n][ks + 2 * tig + 8];
            }
#pragma unroll
            for (int mi = 0; mi < 4; ++mi)
#pragma unroll
                for (int ni = 0; ni < 4; ++ni)
                    mma_f16(acc[mi][ni], af[mi], bf[ni]);
        }
    }

#pragma unroll
    for (int mi = 0; mi < 4; ++mi) {
#pragma unroll
        for (int ni = 0; ni < 4; ++ni) {
            int row = mBase + wm + mi * 16 + gid;
            int col = nBase + wn + ni * 8 + tig * 2;
            float b0 = bias[col], b1 = bias[col + 1];
            float* p0 = g_xproj + (size_t)row * 4096 + col;
            p0[0] = acc[mi][ni][0] + b0;
            p0[1] = acc[mi][ni][1] + b1;
            float* p1 = g_xproj + (size_t)(row + 8) * 4096 + col;
            p1[0] = acc[mi][ni][2] + b0;
            p1[1] = acc[mi][ni][3] + b1;
        }
    }
}

// ----------------------------------------------------------------------------
// init: clear flags; seed g_hh[0] = fp16(h0)
// ----------------------------------------------------------------------------
__global__ void init_kernel(const float* __restrict__ h0) {
    int i = blockIdx.x * 256 + threadIdx.x;          // 4096 threads
    if (i < 128 * 32) g_flags[i] = 0u;
    for (int idx = i; idx < 32 * 1024; idx += 4096)
        g_hh[0][idx >> 10][idx & 1023] = __float2half(h0[idx]);
}

// ----------------------------------------------------------------------------
// Phase 2: persistent recurrence, per-warp dataflow.
// SMEM (dynamic, 173056 B):
//   [0, 66048)            sWhT: fp16 Wh^T [32 n][1032 k]
//   [66048, 132096)       sHh:  fp16 h [32 b][1032 k]  (warp-private columns)
//   [132096, 173056)      part: 8 x 32 x 40 fp32 (separate — no aliasing)
// Warp w: lanes poll producers 16w+(l&15); stage cols [128w,128w+128);
// per-thread cp group wait; mma on own range. 2 block syncs/step.
// ----------------------------------------------------------------------------
static const int ROW_HALVES = 1032;
static const int SWHT_BYTES = 32 * ROW_HALVES * 2;         // 66048
static const int PART_OFF   = 2 * SWHT_BYTES;              // 132096
static const int SMEM_BYTES = PART_OFF + 8 * 32 * 40 * 4;  // 173056

__global__ void __launch_bounds__(256, 1) lstm_persist(
    const float* __restrict__ Wh, float* __restrict__ out)
{
    extern __shared__ __align__(16) char dyn[];
    __half (*sWhT)[ROW_HALVES] = reinterpret_cast<__half (*)[ROW_HALVES]>(dyn);
    __half (*sHh)[ROW_HALVES]  = reinterpret_cast<__half (*)[ROW_HALVES]>(dyn + SWHT_BYTES);
    float (*part)[32][40] = reinterpret_cast<float (*)[32][40]>(dyn + PART_OFF);

    const int tid = threadIdx.x;
    const int cta = blockIdx.x;
    const int c8  = cta * 8;

    // One-time: resident Wh slice as fp16, transposed [n][k].
    for (int idx = tid; idx < 32 * 1024; idx += 256) {
        int k = idx >> 5, col = idx & 31;
        int q = col >> 3, jj = col & 7;
        sWhT[col][k] = __float2half(Wh[(size_t)k * 4096 + q * 1024 + c8 + jj]);
    }
    __syncthreads();

    const int warp = tid >> 5, lane = tid & 31;
    const int gid = lane >> 2, tig = lane & 3;
    const int kw = warp * 128;                  // warp's k-range (halves)
    const int bb = tid >> 3;                    // batch row (epilogue)
    const int jb = tid & 7;                     // gate sub-col (epilogue)
    const int colbase = kw + 8 * (lane & 15);   // this lane's staging column
    const int rhalf   = lane >> 4;              // row phase (0/1)
    const unsigned* myfl = &g_flags[(16 * warp + (lane & 15)) * 32];

    float creg = 0.f;

    for (int t = 0; t < 512; ++t) {
        const __half* hp = &g_hh[t & 1][0][0];

        // Prefetch xproj (DRAM; consumed at epilogue)
        const float* xpp = g_xproj + ((size_t)bb * 512 + t) * 4096 + c8 + jb;
        float xp0 = __ldg(xpp);
        float xp1 = __ldg(xpp + 1024);
        float xp2 = __ldg(xpp + 2048);
        float xp3 = __ldg(xpp + 3072);

        // ---- Per-warp staging: poll own producer, copy own columns ----
        if (t > 0) {
            while (ld_acq_gpu(myfl) < (unsigned)t) { }
        }
#pragma unroll
        for (int k = 0; k < 16; ++k) {
            int r = 2 * k + rhalf;
            cp16cg(&sHh[r][colbase], hp + (size_t)r * 1024 + colbase);
        }
        cp_commit();
        cp_wait<0>();          // per-thread: waits only this warp's copies
        __syncwarp();

        // ---- mma on own k-range (no cross-warp dependency) ----
        float acc[2][4][4];
#pragma unroll
        for (int mi = 0; mi < 2; ++mi)
#pragma unroll
            for (int ni = 0; ni < 4; ++ni)
#pragma unroll
                for (int r = 0; r < 4; ++r) acc[mi][ni][r] = 0.f;

#pragma unroll
        for (int sub = 0; sub < 8; ++sub) {
            const int kg = kw + sub * 16;
            uint32_t af[2][4], bf[4][2];
#pragma unroll
            for (int mi = 0; mi < 2; ++mi) {
                int r = mi * 16 + gid;
                af[mi][0] = *(const uint32_t*)&sHh[r][kg + 2 * tig];
                af[mi][1] = *(const uint32_t*)&sHh[r + 8][kg + 2 * tig];
                af[mi][2] = *(const uint32_t*)&sHh[r][kg + 2 * tig + 8];
                af[mi][3] = *(const uint32_t*)&sHh[r + 8][kg + 2 * tig + 8];
            }
#pragma unroll
            for (int ni = 0; ni < 4; ++ni) {
                int n = ni * 8 + gid;
                bf[ni][0] = *(const uint32_t*)&sWhT[n][kg + 2 * tig];
                bf[ni][1] = *(const uint32_t*)&sWhT[n][kg + 2 * tig + 8];
            }
#pragma unroll
            for (int mi = 0; mi < 2; ++mi)
#pragma unroll
                for (int ni = 0; ni < 4; ++ni)
                    mma_f16(acc[mi][ni], af[mi], bf[ni]);
        }

        // Partials: separate buffer, warp-owned slot -> no pre-sync needed
        // (prior step's readers were released by the end-of-step sync).
#pragma unroll
        for (int mi = 0; mi < 2; ++mi)
#pragma unroll
            for (int ni = 0; ni < 4; ++ni) {
                int r = mi * 16 + gid, c = ni * 8 + tig * 2;
                part[warp][r][c]         = acc[mi][ni][0];
                part[warp][r][c + 1]     = acc[mi][ni][1];
                part[warp][r + 8][c]     = acc[mi][ni][2];
                part[warp][r + 8][c + 1] = acc[mi][ni][3];
            }
        __syncthreads();       // all 8 warps' partials visible

        // Reduce partials + xproj -> gates -> cell -> h_t (coalesced stores)
        float pre[4] = {xp0, xp1, xp2, xp3};
#pragma unroll
        for (int q = 0; q < 4; ++q) {
            int c = q * 8 + jb;
            float s = 0.f;
#pragma unroll
            for (int w = 0; w < 8; ++w) s += part[w][bb][c];
            pre[q] += s;
        }
        float ig = fast_sigmoid(pre[0]);
        float fg = fast_sigmoid(pre[1]);
        float og = fast_sigmoid(pre[2]);
        float gg = fast_tanh(pre[3]);
        creg = fg * creg + ig * gg;
        float hval = og * fast_tanh(creg);
        g_hh[(t + 1) & 1][bb][c8 + jb] = __float2half(hval);
        out[((size_t)bb * 512 + t) * 1024 + c8 + jb] = hval;

        // ---- End-of-step: reduce done (part reusable), stores ordered ----
        __syncthreads();
        if (tid == 0) st_rel_gpu(&g_flags[cta * 32], (unsigned)(t + 1));
    }
}

// ----------------------------------------------------------------------------
extern "C" void kernel_launch(void* const* d_in, const int* in_sizes, int n_in,
                              void* d_out, int out_size)
{
    const float* x  = (const float*)d_in[0];   // (32,512,1024)
    const float* h0 = (const float*)d_in[1];   // (32,1024)
    const float* Wx = (const float*)d_in[2];   // (1024,4096)
    const float* Wh = (const float*)d_in[3];   // (1024,4096)
    const float* b  = (const float*)d_in[4];   // (4096,)
    float* out = (float*)d_out;                // (32,512,1024)

    cudaFuncSetAttribute(lstm_persist,
                         cudaFuncAttributeMaxDynamicSharedMemorySize, SMEM_BYTES);

    conv_x<<<8192, 256>>>(x);
    conv_wt<<<dim3(32, 128), 256>>>(Wx);
    init_kernel<<<16, 256>>>(h0);

    dim3 gA(32, 128);
    xproj16_kernel<<<gA, 256>>>(b);
    lstm_persist<<<128, 256, SMEM_BYTES>>>(Wh, out);
}

// round 14
// speedup vs baseline: 2.9840x; 1.1037x over previous
#include <cuda_runtime.h>
#include <cuda_fp16.h>
#include <cstdint>
#include <cstddef>

// ============================================================================
// LSTM: x (32,512,1024), h0 (32,1024), Wx (1024,4096), Wh (1024,4096), b (4096)
// Phase 0: X -> fp16; Wx -> fp16 transposed [n][k].
// Phase 1: g_xproj = x @ Wx + b — fp16 m16n8k16, LDSM fragments, 3-stage
//          cp.async pipeline with wait_group<1> (one stage always in flight).
// Phase 2: persistent recurrence, per-warp dataflow (R12) + LDSM fragments +
//          2-group k-split staging (overlap fill of k-half 1 with mma half 0).
// ============================================================================

#define DI __device__ __forceinline__

DI uint32_t smem_u32(const void* p) { return (uint32_t)__cvta_generic_to_shared(p); }

DI void cp16cg(const void* smem_dst, const void* gsrc) {
    asm volatile("cp.async.cg.shared.global [%0], [%1], 16;"
                 :: "r"(smem_u32(smem_dst)), "l"(gsrc));
}
DI void cp_commit() { asm volatile("cp.async.commit_group;"); }
template<int N> DI void cp_wait() { asm volatile("cp.async.wait_group %0;" :: "n"(N)); }

DI unsigned ld_acq_gpu(const unsigned* p) {
    unsigned v;
    asm volatile("ld.acquire.gpu.u32 %0, [%1];" : "=r"(v) : "l"(p));
    return v;
}
DI void st_rel_gpu(unsigned* p, unsigned v) {
    asm volatile("st.release.gpu.u32 [%0], %1;" :: "l"(p), "r"(v) : "memory");
}

DI void mma_f16(float* c, const uint32_t* a, const uint32_t* b) {
    asm volatile(
        "mma.sync.aligned.m16n8k16.row.col.f32.f16.f16.f32 "
        "{%0,%1,%2,%3}, {%4,%5,%6,%7}, {%8,%9}, {%0,%1,%2,%3};"
        : "+f"(c[0]), "+f"(c[1]), "+f"(c[2]), "+f"(c[3])
        : "r"(a[0]), "r"(a[1]), "r"(a[2]), "r"(a[3]), "r"(b[0]), "r"(b[1]));
}

DI void ldsm4(uint32_t* r, uint32_t addr) {
    asm volatile("ldmatrix.sync.aligned.m8n8.x4.shared.b16 {%0,%1,%2,%3}, [%4];"
                 : "=r"(r[0]), "=r"(r[1]), "=r"(r[2]), "=r"(r[3]) : "r"(addr));
}

DI float fast_sigmoid(float x) { return 1.f / (1.f + __expf(-x)); }
DI float fast_tanh(float x) {
    float e = __expf(-2.f * x);
    return (1.f - e) / (1.f + e);
}

// Scratch (allocation-free rule: __device__ globals)
__device__ float g_xproj[16384 * 4096];      // 256 MB: (N*T, 4H)
__device__ __half g_x16[16384 * 1024];       // 32 MB: fp16 X
__device__ __half g_wxT16[4096 * 1024];      // 8 MB: fp16 Wx^T [n][k]
__device__ __half g_hh[2][32][1024];         // fp16 h, ping-pong by t parity
__device__ unsigned g_flags[128 * 32];       // per-CTA completed-step counters

// ----------------------------------------------------------------------------
// Phase 0a: X -> fp16. Phase 0b: Wx -> fp16 transposed [n][k].
// ----------------------------------------------------------------------------
__global__ void conv_x(const float* __restrict__ X) {
    size_t i = ((size_t)blockIdx.x * 256 + threadIdx.x) * 8;
    float4 a = *(const float4*)(X + i);
    float4 b = *(const float4*)(X + i + 4);
    __half2 h[4];
    h[0] = __floats2half2_rn(a.x, a.y);
    h[1] = __floats2half2_rn(a.z, a.w);
    h[2] = __floats2half2_rn(b.x, b.y);
    h[3] = __floats2half2_rn(b.z, b.w);
    *(uint4*)(g_x16 + i) = *(const uint4*)h;
}

__global__ void conv_wt(const float* __restrict__ Wx) {
    __shared__ float tile[32][33];
    const int tx = threadIdx.x & 31, ty = threadIdx.x >> 5;
    const int kBase = blockIdx.x * 32;
    const int nBase = blockIdx.y * 32;
#pragma unroll
    for (int r = 0; r < 32; r += 8)
        tile[ty + r][tx] = Wx[(size_t)(kBase + ty + r) * 4096 + nBase + tx];
    __syncthreads();
#pragma unroll
    for (int r = 0; r < 32; r += 8)
        g_wxT16[(size_t)(nBase + ty + r) * 1024 + kBase + tx] =
            __float2half(tile[tx][ty + r]);
}

// ----------------------------------------------------------------------------
// Phase 1: xproj, fp16 m16n8k16 + LDSM. Tile 128x128, BK=32 halves, 3 stages.
// Dynamic smem: 3 stages x {A 128x40h, B 128x40h} = 61440 B. 2 CTAs/SM.
// ----------------------------------------------------------------------------
static const int XP_STAGE = 20480;             // bytes per stage (A+B)
static const int XP_SMEM  = 3 * XP_STAGE;      // 61440

__global__ void __launch_bounds__(256) xproj16_kernel(const float* __restrict__ bias)
{
    extern __shared__ __align__(16) char xsm[];
    auto sA = [&](int s) { return reinterpret_cast<__half(*)[40]>(xsm + s * XP_STAGE); };
    auto sB = [&](int s) { return reinterpret_cast<__half(*)[40]>(xsm + s * XP_STAGE + 10240); };

    const int tid   = threadIdx.x;
    const int mBase = blockIdx.y * 128;
    const int nBase = blockIdx.x * 128;

    auto load_stage = [&](int s, int k0) {     // k0 in halves
#pragma unroll
        for (int i = tid; i < 512; i += 256) {
            int r = i >> 2, c8 = (i & 3) * 8;
            cp16cg(&sA(s)[r][c8], g_x16 + (size_t)(mBase + r) * 1024 + k0 + c8);
        }
#pragma unroll
        for (int i = tid; i < 512; i += 256) {
            int r = i >> 2, c8 = (i & 3) * 8;
            cp16cg(&sB(s)[r][c8], g_wxT16 + (size_t)(nBase + r) * 1024 + k0 + c8);
        }
        cp_commit();
    };

    load_stage(0, 0);
    load_stage(1, 32);

    const int warp = tid >> 5, lane = tid & 31;
    const int wm = (warp >> 2) * 64, wn = (warp & 3) * 32;
    const int gid = lane >> 2, tig = lane & 3;

    // LDSM per-lane row/col offsets
    const int arow = lane & 15;                // + wm + 16*mi
    const int acol = (lane >> 4) * 8;          // + ks
    const int brow = (lane & 7) + ((lane & 16) >> 1);  // + wn + 16*p
    const int bcol = lane & 8;                 // + ks

    float acc[4][4][4];
#pragma unroll
    for (int mi = 0; mi < 4; ++mi)
#pragma unroll
        for (int ni = 0; ni < 4; ++ni)
#pragma unroll
            for (int r = 0; r < 4; ++r) acc[mi][ni][r] = 0.f;

    for (int kt = 0; kt < 32; ++kt) {
        const int cur = kt % 3;
        if (kt < 30) cp_wait<1>(); else cp_wait<0>();
        __syncthreads();
        if (kt < 30) load_stage((kt + 2) % 3, (kt + 2) * 32);

#pragma unroll
        for (int ks = 0; ks < 32; ks += 16) {
            uint32_t af[4][4], bf[4][2];
#pragma unroll
            for (int mi = 0; mi < 4; ++mi)
                ldsm4(af[mi], smem_u32(&sA(cur)[wm + 16 * mi + arow][acol + ks]));
#pragma unroll
            for (int p = 0; p < 2; ++p) {
                uint32_t b4[4];
                ldsm4(b4, smem_u32(&sB(cur)[wn + 16 * p + brow][bcol + ks]));
                bf[2 * p][0] = b4[0]; bf[2 * p][1] = b4[1];
                bf[2 * p + 1][0] = b4[2]; bf[2 * p + 1][1] = b4[3];
            }
#pragma unroll
            for (int mi = 0; mi < 4; ++mi)
#pragma unroll
                for (int ni = 0; ni < 4; ++ni)
                    mma_f16(acc[mi][ni], af[mi], bf[ni]);
        }
    }

#pragma unroll
    for (int mi = 0; mi < 4; ++mi) {
#pragma unroll
        for (int ni = 0; ni < 4; ++ni) {
            int row = mBase + wm + mi * 16 + gid;
            int col = nBase + wn + ni * 8 + tig * 2;
            float b0 = bias[col], b1 = bias[col + 1];
            float* p0 = g_xproj + (size_t)row * 4096 + col;
            p0[0] = acc[mi][ni][0] + b0;
            p0[1] = acc[mi][ni][1] + b1;
            float* p1 = g_xproj + (size_t)(row + 8) * 4096 + col;
            p1[0] = acc[mi][ni][2] + b0;
            p1[1] = acc[mi][ni][3] + b1;
        }
    }
}

// ----------------------------------------------------------------------------
// init: clear flags; seed g_hh[0] = fp16(h0)
// ----------------------------------------------------------------------------
__global__ void init_kernel(const float* __restrict__ h0) {
    int i = blockIdx.x * 256 + threadIdx.x;
    if (i < 128 * 32) g_flags[i] = 0u;
    for (int idx = i; idx < 32 * 1024; idx += 4096)
        g_hh[0][idx >> 10][idx & 1023] = __float2half(h0[idx]);
}

// ----------------------------------------------------------------------------
// Phase 2: persistent recurrence (R12 skeleton) + LDSM + 2-group k-split fill.
// SMEM (dynamic, 173056 B): sWhT 66048 | sHh 66048 | part 40960
// ----------------------------------------------------------------------------
static const int ROW_HALVES = 1032;
static const int SWHT_BYTES = 32 * ROW_HALVES * 2;         // 66048
static const int PART_OFF   = 2 * SWHT_BYTES;              // 132096
static const int SMEM_BYTES = PART_OFF + 8 * 32 * 40 * 4;  // 173056

__global__ void __launch_bounds__(256, 1) lstm_persist(
    const float* __restrict__ Wh, float* __restrict__ out)
{
    extern __shared__ __align__(16) char dyn[];
    __half (*sWhT)[ROW_HALVES] = reinterpret_cast<__half (*)[ROW_HALVES]>(dyn);
    __half (*sHh)[ROW_HALVES]  = reinterpret_cast<__half (*)[ROW_HALVES]>(dyn + SWHT_BYTES);
    float (*part)[32][40] = reinterpret_cast<float (*)[32][40]>(dyn + PART_OFF);

    const int tid = threadIdx.x;
    const int cta = blockIdx.x;
    const int c8  = cta * 8;

    // One-time: resident Wh slice as fp16, transposed [n][k].
    for (int idx = tid; idx < 32 * 1024; idx += 256) {
        int k = idx >> 5, col = idx & 31;
        int q = col >> 3, jj = col & 7;
        sWhT[col][k] = __float2half(Wh[(size_t)k * 4096 + q * 1024 + c8 + jj]);
    }
    __syncthreads();

    const int warp = tid >> 5, lane = tid & 31;
    const int gid = lane >> 2, tig = lane & 3;
    const int kw = warp * 128;                 // warp's k-range (halves)
    const int bb = tid >> 3;                   // batch row (epilogue)
    const int jb = tid & 7;                    // gate sub-col (epilogue)

    // Staging: 2 groups of 8 cp16 per lane. Lane covers k-slice sl (+8 for g1),
    // row phase rph; group g covers k-halves [kw+64g, kw+64g+64).
    const int sl  = lane & 7;
    const int rph = lane >> 3;                 // 0..3
    const unsigned* fl0 = &g_flags[(16 * warp + sl) * 32];
    const unsigned* fl1 = &g_flags[(16 * warp + sl + 8) * 32];
    const int col0 = kw + 8 * sl;
    const int col1 = col0 + 64;

    // LDSM per-lane offsets
    const int arow = lane & 15;
    const int acol = (lane >> 4) * 8;
    const int brow = (lane & 7) + ((lane & 16) >> 1);
    const int bcol = lane & 8;

    float creg = 0.f;

    for (int t = 0; t < 512; ++t) {
        const __half* hp = &g_hh[t & 1][0][0];

        // Prefetch xproj (DRAM; consumed at epilogue)
        const float* xpp = g_xproj + ((size_t)bb * 512 + t) * 4096 + c8 + jb;
        float xp0 = __ldg(xpp);
        float xp1 = __ldg(xpp + 1024);
        float xp2 = __ldg(xpp + 2048);
        float xp3 = __ldg(xpp + 3072);

        // ---- Per-lane producer poll + 2-group staged fill ----
        if (t > 0) { while (ld_acq_gpu(fl0) < (unsigned)t) { } }
#pragma unroll
        for (int c = 0; c < 8; ++c) {
            int r = c * 4 + rph;
            cp16cg(&sHh[r][col0], hp + (size_t)r * 1024 + col0);
        }
        cp_commit();
        if (t > 0) { while (ld_acq_gpu(fl1) < (unsigned)t) { } }
#pragma unroll
        for (int c = 0; c < 8; ++c) {
            int r = c * 4 + rph;
            cp16cg(&sHh[r][col1], hp + (size_t)r * 1024 + col1);
        }
        cp_commit();

        // ---- mma on own k-range; half 0 while half 1 lands ----
        float acc[2][4][4];
#pragma unroll
        for (int mi = 0; mi < 2; ++mi)
#pragma unroll
            for (int ni = 0; ni < 4; ++ni)
#pragma unroll
                for (int r = 0; r < 4; ++r) acc[mi][ni][r] = 0.f;

#pragma unroll
        for (int sub = 0; sub < 8; ++sub) {
            if (sub == 0) { cp_wait<1>(); __syncwarp(); }
            if (sub == 4) { cp_wait<0>(); __syncwarp(); }
            const int kg = kw + sub * 16;
            uint32_t af[2][4], bf[4][2];
#pragma unroll
            for (int mi = 0; mi < 2; ++mi)
                ldsm4(af[mi], smem_u32(&sHh[16 * mi + arow][kg + acol]));
#pragma unroll
            for (int p = 0; p < 2; ++p) {
                uint32_t b4[4];
                ldsm4(b4, smem_u32(&sWhT[16 * p + brow][kg + bcol]));
                bf[2 * p][0] = b4[0]; bf[2 * p][1] = b4[1];
                bf[2 * p + 1][0] = b4[2]; bf[2 * p + 1][1] = b4[3];
            }
#pragma unroll
            for (int mi = 0; mi < 2; ++mi)
#pragma unroll
                for (int ni = 0; ni < 4; ++ni)
                    mma_f16(acc[mi][ni], af[mi], bf[ni]);
        }

        // Partials: separate buffer, warp-owned slot.
#pragma unroll
        for (int mi = 0; mi < 2; ++mi)
#pragma unroll
            for (int ni = 0; ni < 4; ++ni) {
                int r = mi * 16 + gid, c = ni * 8 + tig * 2;
                part[warp][r][c]         = acc[mi][ni][0];
                part[warp][r][c + 1]     = acc[mi][ni][1];
                part[warp][r + 8][c]     = acc[mi][ni][2];
                part[warp][r + 8][c + 1] = acc[mi][ni][3];
            }
        __syncthreads();       // all 8 warps' partials visible

        // Reduce partials + xproj -> gates -> cell -> h_t (coalesced stores)
        float pre[4] = {xp0, xp1, xp2, xp3};
#pragma unroll
        for (int q = 0; q < 4; ++q) {
            int c = q * 8 + jb;
            float s = 0.f;
#pragma unroll
            for (int w = 0; w < 8; ++w) s += part[w][bb][c];
            pre[q] += s;
        }
        float ig = fast_sigmoid(pre[0]);
        float fg = fast_sigmoid(pre[1]);
        float og = fast_sigmoid(pre[2]);
        float gg = fast_tanh(pre[3]);
        creg = fg * creg + ig * gg;
        float hval = og * fast_tanh(creg);
        g_hh[(t + 1) & 1][bb][c8 + jb] = __float2half(hval);
        out[((size_t)bb * 512 + t) * 1024 + c8 + jb] = hval;

        // ---- End-of-step: stores ordered before release ----
        __syncthreads();
        if (tid == 0) st_rel_gpu(&g_flags[cta * 32], (unsigned)(t + 1));
    }
}

// ----------------------------------------------------------------------------
extern "C" void kernel_launch(void* const* d_in, const int* in_sizes, int n_in,
                              void* d_out, int out_size)
{
    const float* x  = (const float*)d_in[0];   // (32,512,1024)
    const float* h0 = (const float*)d_in[1];   // (32,1024)
    const float* Wx = (const float*)d_in[2];   // (1024,4096)
    const float* Wh = (const float*)d_in[3];   // (1024,4096)
    const float* b  = (const float*)d_in[4];   // (4096,)
    float* out = (float*)d_out;                // (32,512,1024)

    cudaFuncSetAttribute(lstm_persist,
                         cudaFuncAttributeMaxDynamicSharedMemorySize, SMEM_BYTES);
    cudaFuncSetAttribute(xproj16_kernel,
                         cudaFuncAttributeMaxDynamicSharedMemorySize, XP_SMEM);

    conv_x<<<8192, 256>>>(x);
    conv_wt<<<dim3(32, 128), 256>>>(Wx);
    init_kernel<<<16, 256>>>(h0);

    dim3 gA(32, 128);                          // n-tiles x m-tiles
    xproj16_kernel<<<gA, 256, XP_SMEM>>>(b);
    lstm_persist<<<128, 256, SMEM_BYTES>>>(Wh, out);
}